// round 13
// baseline (speedup 1.0000x reference)
#include <cuda_runtime.h>

#define BATCH   64
#define NTOK    4096
#define CH      1024
#define KANCH   8
#define NSPLIT  16
#define TOK_PER (NTOK / NSPLIT)   // 256
#define C4      (CH / 4)          // 256 float4 per row

// Scratch (device globals — no allocation allowed).
// __align__(16): accessed through float4*.
__device__ __align__(16) float g_partial[NSPLIT * BATCH * CH];  // 4 MB
__device__ __align__(16) float g_desc[BATCH * CH];              // normalized descriptors
__device__ __align__(16) float g_gram[BATCH * BATCH];           // desc_i . desc_j
__device__ __align__(16) float g_sim[BATCH];                    // desc_b . anchor[ids[b]]
__device__ int      g_ids[BATCH];
__device__ unsigned g_cnt[BATCH];   // per-batch arrival counters
__device__ unsigned g_cnt2;         // gram-row arrival counter
// Counters are monotone: (old % N == N-1) detects the last arrival of THIS
// replay, so no reset is needed and the kernels stay graph-replayable.

// ---------------------------------------------------------------------------
// Fused kernel: streaming partial sums (HBM-bound, 1 GiB) + per-batch
// combiner. The 16th block to finish a batch combines its partials, computes
// the normalized descriptor, cosine sims and argmax — overlapped with the
// rest of the streaming work. ~150-158us at ~86% DRAM (practical ceiling).
// ---------------------------------------------------------------------------
__global__ __launch_bounds__(256, 8) void k_main(const float* __restrict__ x,
                                                 const float* __restrict__ anchors,
                                                 float* __restrict__ out) {
    const int ns = blockIdx.x;
    const int b  = blockIdx.y;
    const int t  = threadIdx.x;  // 0..255 -> channels 4t..4t+3

    // ---- streaming phase (__ldcs: read-once data, evict-first) ----
    {
        const float4* p = reinterpret_cast<const float4*>(x)
                        + (size_t)b * NTOK * C4
                        + (size_t)ns * TOK_PER * C4
                        + t;
        float4 acc = make_float4(0.f, 0.f, 0.f, 0.f);
#pragma unroll 8
        for (int n = 0; n < TOK_PER; ++n) {
            float4 v = __ldcs(p);
            p += C4;
            acc.x += v.x; acc.y += v.y; acc.z += v.z; acc.w += v.w;
        }
        reinterpret_cast<float4*>(g_partial)[(size_t)(ns * BATCH + b) * C4 + t] = acc;
    }

    __threadfence();
    __syncthreads();
    __shared__ unsigned s_old;
    if (t == 0) s_old = atomicAdd(&g_cnt[b], 1u);
    __syncthreads();
    if ((s_old & 15u) != 15u) return;   // not the last arrival for this batch

    __threadfence();   // acquire: order peers' partial stores before our loads

    // ---- combiner phase (one block per batch, 63/64 overlapped) ----
    const int lane = t & 31;
    const int w    = t >> 5;

    float4 s = make_float4(0.f, 0.f, 0.f, 0.f);
#pragma unroll
    for (int nsi = 0; nsi < NSPLIT; ++nsi) {
        float4 v = __ldcg(reinterpret_cast<const float4*>(g_partial)
                          + (size_t)(nsi * BATCH + b) * C4 + t);
        s.x += v.x; s.y += v.y; s.z += v.z; s.w += v.w;
    }
    const float inv_n = 1.0f / (float)NTOK;
    s.x *= inv_n; s.y *= inv_n; s.z *= inv_n; s.w *= inv_n;

    __shared__ float warp_s[8];
    __shared__ float s_invnorm;
    float ss = s.x * s.x + s.y * s.y + s.z * s.z + s.w * s.w;
#pragma unroll
    for (int off = 16; off > 0; off >>= 1)
        ss += __shfl_xor_sync(0xffffffffu, ss, off);
    if (lane == 0) warp_s[w] = ss;
    __syncthreads();
    if (t == 0) {
        float tot = 0.f;
#pragma unroll
        for (int i = 0; i < 8; ++i) tot += warp_s[i];
        s_invnorm = 1.0f / fmaxf(sqrtf(tot), 1e-12f);
    }
    __syncthreads();

    const float invn = s_invnorm;
    float4 d = make_float4(s.x * invn, s.y * invn, s.z * invn, s.w * invn);
    reinterpret_cast<float4*>(g_desc)[(size_t)b * C4 + t] = d;

    float dot[KANCH];
#pragma unroll
    for (int k = 0; k < KANCH; ++k) {
        float4 a = __ldg(reinterpret_cast<const float4*>(anchors) + (size_t)k * C4 + t);
        dot[k] = d.x * a.x + d.y * a.y + d.z * a.z + d.w * a.w;
    }
#pragma unroll
    for (int off = 16; off > 0; off >>= 1) {
#pragma unroll
        for (int k = 0; k < KANCH; ++k)
            dot[k] += __shfl_xor_sync(0xffffffffu, dot[k], off);
    }
    __shared__ float wd[8][KANCH];
    if (lane == 0) {
#pragma unroll
        for (int k = 0; k < KANCH; ++k) wd[w][k] = dot[k];
    }
    __syncthreads();
    if (t == 0) {
        float simk[KANCH];
#pragma unroll
        for (int k = 0; k < KANCH; ++k) {
            float acc = 0.f;
#pragma unroll
            for (int i = 0; i < 8; ++i) acc += wd[i][k];
            simk[k] = acc;
        }
        // argmin(1 - sim) == first max of sim (strict > keeps first occurrence)
        int   best   = 0;
        float best_s = simk[0];
#pragma unroll
        for (int k = 1; k < KANCH; ++k)
            if (simk[k] > best_s) { best_s = simk[k]; best = k; }
        g_ids[b] = best;
        g_sim[b] = best_s;        // a0 . d for the EMA recursion
        out[b]   = (float)best;
    }
}

// ---------------------------------------------------------------------------
// k_tail: Gram + EMA recursion + reconstruction, ONE launch.
// Block i (of 64) computes Gram row i: desc_i staged in smem, 32 warps x 2
// columns each, load-batched. The 64th-arriving block then runs:
//   Phase A: per-anchor lists (chain order preserved)
//   Phase C: warp-per-anchor scalar coefficient recursion (validated math):
//     a_t = (m*a_{t-1} + im*d_t)/r_t, unit-norm d => a_t = c0*a0 + sum c_i d_i
//     p_t = c0*(a0.d_t) + sum_i c_i*G[i][t];  r2 = m^2+im^2+2*m*im*p (in
//     [0.64,1.21] so rsqrtf is exact enough);  c *= m/r, c_t = im/r.
//   Phase D: reconstruction with 4-wide load batching.
// R12 trap root-cause: s_G (shared float[]) was packed at a 4B-aligned offset
// after the 4-byte s_old, and the float4 cast of it issued a misaligned
// LDS.128 -> __align__(16) on s_G.
// ---------------------------------------------------------------------------
__global__ __launch_bounds__(1024) void k_tail(const float* __restrict__ anchors,
                                               const float* __restrict__ counts,
                                               float* __restrict__ out) {
    const int i    = blockIdx.x;        // gram row / block id
    const int t    = threadIdx.x;       // 0..1023
    const int lane = t & 31;
    const int w    = t >> 5;            // warp 0..31

    // ---- Gram row i ----
    __shared__ float4 sdesc[C4];        // desc_i, 4 KB
    if (t < C4)
        sdesc[t] = reinterpret_cast<const float4*>(g_desc)[(size_t)i * C4 + t];
    __syncthreads();

#pragma unroll
    for (int jj = 0; jj < 2; ++jj) {
        const int j = w + jj * 32;
        float acc = 0.f;
#pragma unroll
        for (int k = 0; k < 8; ++k) {
            float4 u = sdesc[k * 32 + lane];
            float4 v = __ldg(reinterpret_cast<const float4*>(g_desc)
                             + (size_t)j * C4 + k * 32 + lane);
            acc += u.x * v.x + u.y * v.y + u.z * v.z + u.w * v.w;
        }
#pragma unroll
        for (int off = 16; off > 0; off >>= 1)
            acc += __shfl_xor_sync(0xffffffffu, acc, off);
        if (lane == 0) g_gram[i * BATCH + j] = acc;
    }

    // ---- arrival counter: last block proceeds to the recursion ----
    __threadfence();
    __syncthreads();
    __shared__ unsigned s_old;
    if (t == 0) s_old = atomicAdd(&g_cnt2, 1u);
    __syncthreads();
    if ((s_old & 63u) != 63u) return;   // not the 64th arrival
    __threadfence();                    // acquire: peers' gram rows visible

    __shared__ __align__(16) float s_G[BATCH * BATCH];  // 16 KB, float4-cast
    __shared__ int   s_list[KANCH][BATCH];
    __shared__ int   s_len[KANCH];
    __shared__ float s_coef[KANCH][BATCH];
    __shared__ float s_c0[KANCH];
    __shared__ float s_sim[BATCH];
    __shared__ int   s_ids[BATCH];

    // Phase A: load Gram (float4-batched) + ids/sims, build per-anchor lists.
    for (int idx = t; idx < BATCH * BATCH / 4; idx += 1024)
        reinterpret_cast<float4*>(s_G)[idx] =
            __ldcg(reinterpret_cast<const float4*>(g_gram) + idx);
    if (t < BATCH) { s_ids[t] = g_ids[t]; s_sim[t] = g_sim[t]; }
    __syncthreads();
    if (t < KANCH) {
        int n = 0;
        for (int b = 0; b < BATCH; ++b)
            if (s_ids[b] == t) s_list[t][n++] = b;
        s_len[t] = n;
    }
    __syncthreads();

    // Phase C: warp-per-anchor scalar recursion (warps 0..7).
    if (w < KANCH) {
        const int g = w;
        const int L = s_len[g];
        float c  = __ldg(counts + g);
        float c0 = 1.0f;
        for (int st = 0; st < L; ++st) {
            const int bt = s_list[g][st];
            const float m  = (c < 1.0f) ? 0.0f : 0.9f;
            const float im = 1.0f - m;

            float part = 0.f;
            for (int ii = lane; ii < st; ii += 32)
                part += s_coef[g][ii] * s_G[s_list[g][ii] * BATCH + bt];
#pragma unroll
            for (int off = 16; off > 0; off >>= 1)
                part += __shfl_xor_sync(0xffffffffu, part, off);

            const float p     = c0 * s_sim[bt] + part;
            const float r2    = m * m + im * im + 2.0f * m * im * p;
            const float inv_r = rsqrtf(r2);     // r2 in [0.64,1.21]
            const float sc    = m * inv_r;

            c0 *= sc;
            for (int ii = lane; ii < st; ii += 32) s_coef[g][ii] *= sc;
            if (lane == 0) s_coef[g][st] = im * inv_r;
            c += 1.0f;
            __syncwarp();
        }
        if (lane == 0) {
            s_c0[g] = c0;
            out[BATCH + KANCH * CH + g] = c;   // new counts
        }
    }
    __syncthreads();

    // Phase D: reconstruct anchors. Thread t owns channel t; 4-wide manual
    // load batching (addresses independent of acc -> MLP 4).
    for (int g = 0; g < KANCH; ++g) {
        float acc = s_c0[g] * __ldg(anchors + (size_t)g * CH + t);
        const int L = s_len[g];
        int ii = 0;
        for (; ii + 4 <= L; ii += 4) {
            const int b0 = s_list[g][ii],     b1 = s_list[g][ii + 1];
            const int b2 = s_list[g][ii + 2], b3 = s_list[g][ii + 3];
            const float v0 = g_desc[(size_t)b0 * CH + t];
            const float v1 = g_desc[(size_t)b1 * CH + t];
            const float v2 = g_desc[(size_t)b2 * CH + t];
            const float v3 = g_desc[(size_t)b3 * CH + t];
            acc += s_coef[g][ii]     * v0;
            acc += s_coef[g][ii + 1] * v1;
            acc += s_coef[g][ii + 2] * v2;
            acc += s_coef[g][ii + 3] * v3;
        }
        for (; ii < L; ++ii)
            acc += s_coef[g][ii] * g_desc[(size_t)s_list[g][ii] * CH + t];
        out[BATCH + g * CH + t] = acc;
    }
}

// ---------------------------------------------------------------------------
extern "C" void kernel_launch(void* const* d_in, const int* in_sizes, int n_in,
                              void* d_out, int out_size) {
    const float* prompt_tokens = (const float*)d_in[0];  // [64,4096,1024] f32
    const float* anchors       = (const float*)d_in[1];  // [8,1024] f32
    const float* counts        = (const float*)d_in[2];  // [8] f32
    float* out = (float*)d_out;  // [64 ids | 8192 anchors | 8 counts] f32

    dim3 grid1(NSPLIT, BATCH);
    k_main<<<grid1, 256>>>(prompt_tokens, anchors, out);
    k_tail<<<BATCH, 1024>>>(anchors, counts, out);
}

// round 14
// speedup vs baseline: 1.1118x; 1.1118x over previous
#include <cuda_runtime.h>

#define BATCH   64
#define NTOK    4096
#define CH      1024
#define KANCH   8
#define NSPLIT  16
#define TOK_PER (NTOK / NSPLIT)   // 256
#define C4      (CH / 4)          // 256 float4 per row

// Scratch (device globals — no allocation allowed).
// __align__(16): accessed through float4* (R11/R12 trapped without it).
__device__ __align__(16) float g_partial[NSPLIT * BATCH * CH];  // 4 MB
__device__ __align__(16) float g_desc[BATCH * CH];              // normalized descriptors
__device__ int      g_ids[BATCH];
__device__ unsigned g_cnt[BATCH];   // per-batch arrival counters
// Counters are monotone: (old % 16 == 15) detects the last arrival of THIS
// replay, so no reset is needed and the kernels stay graph-replayable.

// ---------------------------------------------------------------------------
// Fused kernel: streaming partial sums (HBM-bound, 1 GiB) + per-batch
// combiner. The 16th block to finish a batch combines its partials, computes
// the normalized descriptor, cosine sims and argmax — overlapped with the
// rest of the streaming work. ~150-158us at ~86% DRAM (practical ceiling).
// ---------------------------------------------------------------------------
__global__ __launch_bounds__(256, 8) void k_main(const float* __restrict__ x,
                                                 const float* __restrict__ anchors,
                                                 float* __restrict__ out) {
    const int ns = blockIdx.x;
    const int b  = blockIdx.y;
    const int t  = threadIdx.x;  // 0..255 -> channels 4t..4t+3

    // ---- streaming phase (__ldcs: read-once data, evict-first) ----
    {
        const float4* p = reinterpret_cast<const float4*>(x)
                        + (size_t)b * NTOK * C4
                        + (size_t)ns * TOK_PER * C4
                        + t;
        float4 acc = make_float4(0.f, 0.f, 0.f, 0.f);
#pragma unroll 8
        for (int n = 0; n < TOK_PER; ++n) {
            float4 v = __ldcs(p);
            p += C4;
            acc.x += v.x; acc.y += v.y; acc.z += v.z; acc.w += v.w;
        }
        reinterpret_cast<float4*>(g_partial)[(size_t)(ns * BATCH + b) * C4 + t] = acc;
    }

    __threadfence();
    __syncthreads();
    __shared__ unsigned s_old;
    if (t == 0) s_old = atomicAdd(&g_cnt[b], 1u);
    __syncthreads();
    if ((s_old & 15u) != 15u) return;   // not the last arrival for this batch

    __threadfence();   // acquire: order peers' partial stores before our loads

    // ---- combiner phase (one block per batch, 63/64 overlapped) ----
    const int lane = t & 31;
    const int w    = t >> 5;

    float4 s = make_float4(0.f, 0.f, 0.f, 0.f);
#pragma unroll
    for (int nsi = 0; nsi < NSPLIT; ++nsi) {
        float4 v = __ldcg(reinterpret_cast<const float4*>(g_partial)
                          + (size_t)(nsi * BATCH + b) * C4 + t);
        s.x += v.x; s.y += v.y; s.z += v.z; s.w += v.w;
    }
    const float inv_n = 1.0f / (float)NTOK;
    s.x *= inv_n; s.y *= inv_n; s.z *= inv_n; s.w *= inv_n;

    __shared__ float warp_s[8];
    __shared__ float s_invnorm;
    float ss = s.x * s.x + s.y * s.y + s.z * s.z + s.w * s.w;
#pragma unroll
    for (int off = 16; off > 0; off >>= 1)
        ss += __shfl_xor_sync(0xffffffffu, ss, off);
    if (lane == 0) warp_s[w] = ss;
    __syncthreads();
    if (t == 0) {
        float tot = 0.f;
#pragma unroll
        for (int i = 0; i < 8; ++i) tot += warp_s[i];
        s_invnorm = 1.0f / fmaxf(sqrtf(tot), 1e-12f);
    }
    __syncthreads();

    const float invn = s_invnorm;
    float4 d = make_float4(s.x * invn, s.y * invn, s.z * invn, s.w * invn);
    reinterpret_cast<float4*>(g_desc)[(size_t)b * C4 + t] = d;

    float dot[KANCH];
#pragma unroll
    for (int k = 0; k < KANCH; ++k) {
        float4 a = __ldg(reinterpret_cast<const float4*>(anchors) + (size_t)k * C4 + t);
        dot[k] = d.x * a.x + d.y * a.y + d.z * a.z + d.w * a.w;
    }
#pragma unroll
    for (int off = 16; off > 0; off >>= 1) {
#pragma unroll
        for (int k = 0; k < KANCH; ++k)
            dot[k] += __shfl_xor_sync(0xffffffffu, dot[k], off);
    }
    __shared__ float wd[8][KANCH];
    if (lane == 0) {
#pragma unroll
        for (int k = 0; k < KANCH; ++k) wd[w][k] = dot[k];
    }
    __syncthreads();
    if (t == 0) {
        float simk[KANCH];
#pragma unroll
        for (int k = 0; k < KANCH; ++k) {
            float acc = 0.f;
#pragma unroll
            for (int i = 0; i < 8; ++i) acc += wd[i][k];
            simk[k] = acc;
        }
        // argmin(1 - sim) == first max of sim (strict > keeps first occurrence)
        int   best   = 0;
        float best_s = simk[0];
#pragma unroll
        for (int k = 1; k < KANCH; ++k)
            if (simk[k] > best_s) { best_s = simk[k]; best = k; }
        g_ids[b] = best;
        out[b]   = (float)best;
    }
}

// ---------------------------------------------------------------------------
// k_ema2: direct warp-per-anchor EMA (8 independent chains; in-chain batch
// order preserved => equivalent to the sequential scan).
// Fixes for R6's 17.7us version:
//  * anchor state in SHARED (not regs) -> the 8-wide descriptor load buffer
//    fits in registers and batches (MLP 8) instead of serializing at MLP 1.
//  * unnormalized state + warp-uniform scalar: a_true = scale * raw. Step:
//      v = (m*scale)*raw + im*d ; raw' = v ; scale' = rsqrtf(|v|^2)
//    -> ONE vector pass per step (normalize is a scalar).  r^2 in [0.64,1.21]
//    (m=0.9 worst antiparallel: 0.8) so the 1e-12 guard never binds.
//  * single-buffer prefetch: next sample's d loads issue right after current
//    d is consumed, overlapping the shfl reduce.
// ---------------------------------------------------------------------------
__global__ __launch_bounds__(256) void k_ema2(const float* __restrict__ anchors,
                                              const float* __restrict__ counts,
                                              float* __restrict__ out) {
    __shared__ __align__(16) float sA[KANCH * CH];   // 32 KB, float4-accessed
    __shared__ int s_list[KANCH][BATCH];
    __shared__ int s_len[KANCH];

    const int t    = threadIdx.x;   // 0..255
    const int lane = t & 31;
    const int g    = t >> 5;        // warp = anchor id, 0..7

    // Build per-anchor sample lists (order preserved) + stage anchors.
    if (t < KANCH) {
        int n = 0;
        for (int b = 0; b < BATCH; ++b)
            if (g_ids[b] == t) s_list[t][n++] = b;
        s_len[t] = n;
    }
    for (int idx = t; idx < KANCH * C4; idx += 256)
        reinterpret_cast<float4*>(sA)[idx] =
            __ldg(reinterpret_cast<const float4*>(anchors) + idx);
    __syncthreads();

    const int len = s_len[g];
    float scale = 1.0f;             // a_true = scale * sA-row
    float c     = __ldg(counts + g);

    // Prefetch descriptor for the first chain sample (8 batched float4 LDGs).
    float4 d[8];
    if (len > 0) {
        const int b0 = s_list[g][0];
#pragma unroll
        for (int j = 0; j < 8; ++j)
            d[j] = __ldg(reinterpret_cast<const float4*>(g_desc)
                         + (size_t)b0 * C4 + j * 32 + lane);
    }

    float4* aRow = reinterpret_cast<float4*>(sA) + g * C4;   // this warp's anchor

    for (int i = 0; i < len; ++i) {
        const float m  = (c < 1.0f) ? 0.0f : 0.9f;
        const float im = 1.0f - m;
        const float ma = m * scale;

        float s0 = 0.f, s1 = 0.f, s2 = 0.f, s3 = 0.f;
#pragma unroll
        for (int j = 0; j < 8; ++j) {
            float4 a = aRow[j * 32 + lane];            // LDS
            float4 v;
            v.x = ma * a.x + im * d[j].x;
            v.y = ma * a.y + im * d[j].y;
            v.z = ma * a.z + im * d[j].z;
            v.w = ma * a.w + im * d[j].w;
            aRow[j * 32 + lane] = v;                   // STS (raw, unnormalized)
            s0 += v.x * v.x; s1 += v.y * v.y;
            s2 += v.z * v.z; s3 += v.w * v.w;
        }

        // Prefetch next sample's descriptor; overlaps the reduce below.
        if (i + 1 < len) {
            const int bn = s_list[g][i + 1];
#pragma unroll
            for (int j = 0; j < 8; ++j)
                d[j] = __ldg(reinterpret_cast<const float4*>(g_desc)
                             + (size_t)bn * C4 + j * 32 + lane);
        }

        float ssum = (s0 + s1) + (s2 + s3);
#pragma unroll
        for (int off = 16; off > 0; off >>= 1)
            ssum += __shfl_xor_sync(0xffffffffu, ssum, off);
        scale = rsqrtf(ssum);       // |v| in [0.8, 1.1]; eps guard never binds
        c += 1.0f;
    }

    // Emit new_anchors (scale applied) then new_counts.
#pragma unroll
    for (int j = 0; j < 8; ++j) {
        float4 v = aRow[j * 32 + lane];
        v.x *= scale; v.y *= scale; v.z *= scale; v.w *= scale;
        reinterpret_cast<float4*>(out + BATCH)[(size_t)g * C4 + j * 32 + lane] = v;
    }
    if (lane == 0) out[BATCH + KANCH * CH + g] = c;
}

// ---------------------------------------------------------------------------
extern "C" void kernel_launch(void* const* d_in, const int* in_sizes, int n_in,
                              void* d_out, int out_size) {
    const float* prompt_tokens = (const float*)d_in[0];  // [64,4096,1024] f32
    const float* anchors       = (const float*)d_in[1];  // [8,1024] f32
    const float* counts        = (const float*)d_in[2];  // [8] f32
    float* out = (float*)d_out;  // [64 ids | 8192 anchors | 8 counts] f32

    dim3 grid1(NSPLIT, BATCH);
    k_main<<<grid1, 256>>>(prompt_tokens, anchors, out);
    k_ema2<<<1, 256>>>(anchors, counts, out);
}